// round 12
// baseline (speedup 1.0000x reference)
#include <cuda_runtime.h>
#include <cuda_bf16.h>
#include <math.h>

// Problem constants (fixed by setup_inputs: N=8192, D=512, C=64)
#define N_ROWS 8192
#define DIM    512
#define NCLS   64

// ---------------- device scratch (no allocations allowed) ----------------
__device__ int    g_lbl[N_ROWS];
__device__ float  g_sq[N_ROWS];
__device__ int    g_hist[NCLS];
__device__ int    g_off[NCLS + 1];
__device__ int    g_cursor[NCLS];
__device__ int    g_members[N_ROWS];
__device__ int    g_m1;
__device__ int    g_m2;
__device__ double g_sameSum;
__device__ double g_sameCnt;
__device__ double g_hingeSum;

// ---------------- K0: zero the accumulators ----------------
__global__ void k_init() {
    int t = threadIdx.x;
    if (t < NCLS) g_hist[t] = 0;
    if (t == 0) {
        g_sameSum  = 0.0;
        g_sameCnt  = 0.0;
        g_hingeSum = 0.0;
        g_m1 = -1;
        g_m2 = -1;
    }
}

// ---------------- K1: per-row argmax(labels) + sum-of-squares(outputs) ----
// One warp per row. labels row = 64 floats (2/lane); outputs row = 512 floats
// (4 float4 per lane).
__global__ void k_row(const float* __restrict__ outputs,
                      const float* __restrict__ labels) {
    int warp = (blockIdx.x * blockDim.x + threadIdx.x) >> 5;
    int lane = threadIdx.x & 31;
    if (warp >= N_ROWS) return;

    // ---- argmax over 64 labels, first-max wins on ties (jnp.argmax) ----
    const float* lr = labels + (size_t)warp * NCLS;
    float v0 = lr[lane];
    float v1 = lr[lane + 32];
    float bv; int bi;
    if (v0 >= v1) { bv = v0; bi = lane; } else { bv = v1; bi = lane + 32; }
    #pragma unroll
    for (int s = 16; s > 0; s >>= 1) {
        float ov = __shfl_down_sync(0xffffffffu, bv, s);
        int   oi = __shfl_down_sync(0xffffffffu, bi, s);
        if (ov > bv || (ov == bv && oi < bi)) { bv = ov; bi = oi; }
    }
    bi = __shfl_sync(0xffffffffu, bi, 0);

    // ---- sum of squares over 512 dims ----
    const float4* xr = (const float4*)(outputs + (size_t)warp * DIM);
    float s = 0.f;
    #pragma unroll
    for (int k = lane; k < DIM / 4; k += 32) {
        float4 v = xr[k];
        s += v.x * v.x + v.y * v.y + v.z * v.z + v.w * v.w;
    }
    #pragma unroll
    for (int sh = 16; sh > 0; sh >>= 1)
        s += __shfl_down_sync(0xffffffffu, s, sh);

    if (lane == 0) {
        g_lbl[warp] = bi;
        g_sq[warp]  = s;
        atomicAdd(&g_hist[bi], 1);
    }
}

// ---------------- K2: scan histogram, find m1/m2, same-pair count --------
__global__ void k_scan() {
    if (threadIdx.x != 0) return;
    int acc = 0, m1 = -1, m2 = -1;
    double scnt = 0.0;
    for (int c = 0; c < NCLS; c++) {
        g_off[c]    = acc;
        g_cursor[c] = acc;
        int n = g_hist[c];
        acc += n;
        if (n > 0) { m2 = m1; m1 = c; }
        scnt += (double)n * (double)(n - 1) * 0.5;
    }
    g_off[NCLS] = acc;
    g_m1 = m1;
    g_m2 = m2;
    g_sameCnt = scnt;
}

// ---------------- K3: scatter row indices grouped by class ---------------
__global__ void k_scatter() {
    int i = blockIdx.x * blockDim.x + threadIdx.x;
    if (i >= N_ROWS) return;
    int c = g_lbl[i];
    int pos = atomicAdd(&g_cursor[c], 1);
    g_members[pos] = i;
}

// ---------------- K4: per-class sums -> same-class loss numerator --------
// Sum_{i<j in c} d2 = n_c * S_c - ||M_c||^2   (max(.,0) never binds here:
// min same-pair d2 for this data is ~7e2, far above 0).
// One block per class, 512 threads = one per dim. Coalesced row streaming.
__global__ void k_class(const float* __restrict__ outputs) {
    __shared__ int    s_idx[512];     // class member cache (chunked)
    __shared__ double s_red[512];

    int c   = blockIdx.x;
    int beg = g_off[c];
    int end = g_off[c + 1];
    int n   = end - beg;
    int d   = threadIdx.x;

    float m = 0.f, ssq = 0.f;
    for (int base = beg; base < end; base += 512) {
        int chunk = min(512, end - base);
        __syncthreads();
        if (d < chunk) s_idx[d] = g_members[base + d];
        __syncthreads();
        for (int k = 0; k < chunk; k++) {
            float x = outputs[(size_t)s_idx[k] * DIM + d];
            m   += x;
            ssq += x * x;
        }
    }
    __syncthreads();

    // reduce ||M||^2
    s_red[d] = (double)m * (double)m;
    __syncthreads();
    #pragma unroll
    for (int s = 256; s > 0; s >>= 1) {
        if (d < s) s_red[d] += s_red[d + s];
        __syncthreads();
    }
    double Msq = s_red[0];
    __syncthreads();

    // reduce S_c
    s_red[d] = (double)ssq;
    __syncthreads();
    #pragma unroll
    for (int s = 256; s > 0; s >>= 1) {
        if (d < s) s_red[d] += s_red[d + s];
        __syncthreads();
    }
    if (d == 0 && n > 1) {
        double Sc = s_red[0];
        atomicAdd(&g_sameSum, (double)n * Sc - Msq);
    }
}

// ---------------- K5: cross-class hinge (class m2 rows x class m1 cols) --
// One warp per pair, grid-stride. Working set ~512 KB -> L2 resident.
__global__ void k_cross(const float* __restrict__ outputs) {
    int m1 = g_m1, m2 = g_m2;
    if (m1 < 0 || m2 < 0) return;
    int off1 = g_off[m1], n1 = g_hist[m1];
    int off2 = g_off[m2], n2 = g_hist[m2];
    long long P = (long long)n1 * (long long)n2;
    if (P == 0) return;

    int lane = threadIdx.x & 31;
    long long warp  = (long long)((blockIdx.x * blockDim.x + threadIdx.x) >> 5);
    long long nwarp = (long long)((gridDim.x * blockDim.x) >> 5);

    double hsum = 0.0;
    for (long long p = warp; p < P; p += nwarp) {
        int i = g_members[off2 + (int)(p / n1)];   // class m2
        int j = g_members[off1 + (int)(p % n1)];   // class m1
        const float4* xi = (const float4*)(outputs + (size_t)i * DIM);
        const float4* xj = (const float4*)(outputs + (size_t)j * DIM);
        float dot = 0.f;
        #pragma unroll
        for (int k = lane; k < DIM / 4; k += 32) {
            float4 a = xi[k];
            float4 b = xj[k];
            dot += a.x * b.x + a.y * b.y + a.z * b.z + a.w * b.w;
        }
        #pragma unroll
        for (int sh = 16; sh > 0; sh >>= 1)
            dot += __shfl_down_sync(0xffffffffu, dot, sh);
        if (lane == 0) {
            float d2 = fmaxf(g_sq[i] + g_sq[j] - 2.f * dot, 0.f);
            float h  = fmaxf(1.0f - sqrtf(d2), 0.f);
            hsum += (double)h * (double)h;
        }
    }
    if (lane == 0) atomicAdd(&g_hingeSum, hsum);
}

// ---------------- K6: finalize -------------------------------------------
__global__ void k_final(float* __restrict__ out) {
    if (threadIdx.x != 0 || blockIdx.x != 0) return;
    double same = (g_sameCnt > 0.0) ? (g_sameSum / g_sameCnt) : 0.0;
    double total_pairs = (double)N_ROWS * (double)(N_ROWS - 1) * 0.5;
    out[0] = (float)(same + g_hingeSum / total_pairs);
}

extern "C" void kernel_launch(void* const* d_in, const int* in_sizes, int n_in,
                              void* d_out, int out_size) {
    const float* outputs = (const float*)d_in[0];   // [8192, 512] f32
    const float* labels  = (const float*)d_in[1];   // [8192, 64]  f32
    float* out = (float*)d_out;
    (void)in_sizes; (void)n_in; (void)out_size;

    k_init<<<1, 64>>>();
    k_row<<<N_ROWS / 8, 256>>>(outputs, labels);    // 8 warps/block, warp/row
    k_scan<<<1, 32>>>();
    k_scatter<<<N_ROWS / 256, 256>>>();
    k_class<<<NCLS, 512>>>(outputs);
    k_cross<<<256, 256>>>(outputs);
    k_final<<<1, 32>>>(out);
}

// round 13
// speedup vs baseline: 1.0297x; 1.0297x over previous
#include <cuda_runtime.h>
#include <cuda_bf16.h>
#include <math.h>

// Problem constants (fixed by setup_inputs: N=8192, D=512, C=64)
#define N_ROWS 8192
#define DIM    512
#define NCLS   64

// ---------------- device scratch (no allocations allowed) ----------------
__device__ int    g_lbl[N_ROWS];
__device__ float  g_sq[N_ROWS];
__device__ int    g_hist[NCLS];
__device__ int    g_off[NCLS + 1];
__device__ int    g_cursor[NCLS];
__device__ int    g_members[N_ROWS];
__device__ int    g_m1;
__device__ int    g_m2;
__device__ double g_sameSum;
__device__ double g_sameCnt;
__device__ double g_hingeSum;

// ---------------- K0: zero the accumulators ----------------
__global__ void k_init() {
    int t = threadIdx.x;
    if (t < NCLS) g_hist[t] = 0;
    if (t == 0) {
        g_sameSum  = 0.0;
        g_sameCnt  = 0.0;
        g_hingeSum = 0.0;
        g_m1 = -1;
        g_m2 = -1;
    }
}

// ---------------- K1: per-row argmax(labels) + sum-of-squares(outputs) ----
// One warp per row. labels row = 64 floats (2/lane); outputs row = 512 floats
// (4 float4 per lane).
__global__ void k_row(const float* __restrict__ outputs,
                      const float* __restrict__ labels) {
    int warp = (blockIdx.x * blockDim.x + threadIdx.x) >> 5;
    int lane = threadIdx.x & 31;
    if (warp >= N_ROWS) return;

    // ---- argmax over 64 labels, first-max wins on ties (jnp.argmax) ----
    const float* lr = labels + (size_t)warp * NCLS;
    float v0 = lr[lane];
    float v1 = lr[lane + 32];
    float bv; int bi;
    if (v0 >= v1) { bv = v0; bi = lane; } else { bv = v1; bi = lane + 32; }
    #pragma unroll
    for (int s = 16; s > 0; s >>= 1) {
        float ov = __shfl_down_sync(0xffffffffu, bv, s);
        int   oi = __shfl_down_sync(0xffffffffu, bi, s);
        if (ov > bv || (ov == bv && oi < bi)) { bv = ov; bi = oi; }
    }
    bi = __shfl_sync(0xffffffffu, bi, 0);

    // ---- sum of squares over 512 dims ----
    const float4* xr = (const float4*)(outputs + (size_t)warp * DIM);
    float s = 0.f;
    #pragma unroll
    for (int k = lane; k < DIM / 4; k += 32) {
        float4 v = xr[k];
        s += v.x * v.x + v.y * v.y + v.z * v.z + v.w * v.w;
    }
    #pragma unroll
    for (int sh = 16; sh > 0; sh >>= 1)
        s += __shfl_down_sync(0xffffffffu, s, sh);

    if (lane == 0) {
        g_lbl[warp] = bi;
        g_sq[warp]  = s;
        atomicAdd(&g_hist[bi], 1);
    }
}

// ---------------- K2: scan histogram, find m1/m2, same-pair count --------
__global__ void k_scan() {
    if (threadIdx.x != 0) return;
    int acc = 0, m1 = -1, m2 = -1;
    double scnt = 0.0;
    for (int c = 0; c < NCLS; c++) {
        g_off[c]    = acc;
        g_cursor[c] = acc;
        int n = g_hist[c];
        acc += n;
        if (n > 0) { m2 = m1; m1 = c; }
        scnt += (double)n * (double)(n - 1) * 0.5;
    }
    g_off[NCLS] = acc;
    g_m1 = m1;
    g_m2 = m2;
    g_sameCnt = scnt;
}

// ---------------- K3: scatter row indices grouped by class ---------------
__global__ void k_scatter() {
    int i = blockIdx.x * blockDim.x + threadIdx.x;
    if (i >= N_ROWS) return;
    int c = g_lbl[i];
    int pos = atomicAdd(&g_cursor[c], 1);
    g_members[pos] = i;
}

// ---------------- K4: per-class sums -> same-class loss numerator --------
// Sum_{i<j in c} d2 = n_c * S_c - ||M_c||^2   (max(.,0) never binds here:
// min same-pair d2 for this data is ~7e2, far above 0).
// One block per class, 512 threads = one per dim. Coalesced row streaming.
__global__ void k_class(const float* __restrict__ outputs) {
    __shared__ int    s_idx[512];     // class member cache (chunked)
    __shared__ double s_red[512];

    int c   = blockIdx.x;
    int beg = g_off[c];
    int end = g_off[c + 1];
    int n   = end - beg;
    int d   = threadIdx.x;

    float m = 0.f, ssq = 0.f;
    for (int base = beg; base < end; base += 512) {
        int chunk = min(512, end - base);
        __syncthreads();
        if (d < chunk) s_idx[d] = g_members[base + d];
        __syncthreads();
        for (int k = 0; k < chunk; k++) {
            float x = outputs[(size_t)s_idx[k] * DIM + d];
            m   += x;
            ssq += x * x;
        }
    }
    __syncthreads();

    // reduce ||M||^2
    s_red[d] = (double)m * (double)m;
    __syncthreads();
    #pragma unroll
    for (int s = 256; s > 0; s >>= 1) {
        if (d < s) s_red[d] += s_red[d + s];
        __syncthreads();
    }
    double Msq = s_red[0];
    __syncthreads();

    // reduce S_c
    s_red[d] = (double)ssq;
    __syncthreads();
    #pragma unroll
    for (int s = 256; s > 0; s >>= 1) {
        if (d < s) s_red[d] += s_red[d + s];
        __syncthreads();
    }
    if (d == 0 && n > 1) {
        double Sc = s_red[0];
        atomicAdd(&g_sameSum, (double)n * Sc - Msq);
    }
}

// ---------------- K5: cross-class hinge (class m2 rows x class m1 cols) --
// One warp per pair, grid-stride. Working set ~512 KB -> L2 resident.
__global__ void k_cross(const float* __restrict__ outputs) {
    int m1 = g_m1, m2 = g_m2;
    if (m1 < 0 || m2 < 0) return;
    int off1 = g_off[m1], n1 = g_hist[m1];
    int off2 = g_off[m2], n2 = g_hist[m2];
    long long P = (long long)n1 * (long long)n2;
    if (P == 0) return;

    int lane = threadIdx.x & 31;
    long long warp  = (long long)((blockIdx.x * blockDim.x + threadIdx.x) >> 5);
    long long nwarp = (long long)((gridDim.x * blockDim.x) >> 5);

    double hsum = 0.0;
    for (long long p = warp; p < P; p += nwarp) {
        int i = g_members[off2 + (int)(p / n1)];   // class m2
        int j = g_members[off1 + (int)(p % n1)];   // class m1
        const float4* xi = (const float4*)(outputs + (size_t)i * DIM);
        const float4* xj = (const float4*)(outputs + (size_t)j * DIM);
        float dot = 0.f;
        #pragma unroll
        for (int k = lane; k < DIM / 4; k += 32) {
            float4 a = xi[k];
            float4 b = xj[k];
            dot += a.x * b.x + a.y * b.y + a.z * b.z + a.w * b.w;
        }
        #pragma unroll
        for (int sh = 16; sh > 0; sh >>= 1)
            dot += __shfl_down_sync(0xffffffffu, dot, sh);
        if (lane == 0) {
            float d2 = fmaxf(g_sq[i] + g_sq[j] - 2.f * dot, 0.f);
            float h  = fmaxf(1.0f - sqrtf(d2), 0.f);
            hsum += (double)h * (double)h;
        }
    }
    if (lane == 0) atomicAdd(&g_hingeSum, hsum);
}

// ---------------- K6: finalize -------------------------------------------
__global__ void k_final(float* __restrict__ out) {
    if (threadIdx.x != 0 || blockIdx.x != 0) return;
    double same = (g_sameCnt > 0.0) ? (g_sameSum / g_sameCnt) : 0.0;
    double total_pairs = (double)N_ROWS * (double)(N_ROWS - 1) * 0.5;
    out[0] = (float)(same + g_hingeSum / total_pairs);
}

extern "C" void kernel_launch(void* const* d_in, const int* in_sizes, int n_in,
                              void* d_out, int out_size) {
    const float* outputs = (const float*)d_in[0];   // [8192, 512] f32
    const float* labels  = (const float*)d_in[1];   // [8192, 64]  f32
    float* out = (float*)d_out;
    (void)in_sizes; (void)n_in; (void)out_size;

    k_init<<<1, 64>>>();
    k_row<<<N_ROWS / 8, 256>>>(outputs, labels);    // 8 warps/block, warp/row
    k_scan<<<1, 32>>>();
    k_scatter<<<N_ROWS / 256, 256>>>();
    k_class<<<NCLS, 512>>>(outputs);
    k_cross<<<256, 256>>>(outputs);
    k_final<<<1, 32>>>(out);
}

// round 14
// speedup vs baseline: 1.1620x; 1.1285x over previous
#include <cuda_runtime.h>
#include <cuda_bf16.h>
#include <math.h>

// Problem constants (fixed by setup_inputs: N=8192, D=512, C=64)
#define N_ROWS 8192
#define DIM    512
#define NCLS   64
#define NB     148        // persistent blocks, one per SM (GB300 has 152)
#define NT     512

// ---------------- device scratch (no allocations allowed) ----------------
__device__ int    g_lbl[N_ROWS];
__device__ float  g_sq[N_ROWS];
__device__ int    g_hist[NCLS];       // must be zero at phase-1 entry (reset at end of run)
__device__ int    g_off[NCLS + 1];
__device__ int    g_cursor[NCLS];
__device__ int    g_members[N_ROWS];
__device__ int    g_m1, g_m2;
__device__ double g_sameSum;          // reset at end of run
__device__ double g_sameCnt;
__device__ double g_hingeSum;         // reset at end of run
__device__ unsigned g_barCount = 0;   // returns to 0 after every barrier
__device__ unsigned g_barGen   = 0;   // monotonically increasing generation

// Grid-wide barrier: 1 arrival per block (single-lane REDG ~1cyc at LTS),
// spin on generation word with volatile loads (L2 reads, not atomics).
__device__ __forceinline__ void grid_sync() {
    __syncthreads();
    if (threadIdx.x == 0) {
        __threadfence();                                   // publish my writes
        unsigned gen = *((volatile unsigned*)&g_barGen);   // read BEFORE arriving
        unsigned t = atomicAdd(&g_barCount, 1u);
        if (t == NB - 1) {
            atomicExch(&g_barCount, 0u);
            __threadfence();
            atomicAdd(&g_barGen, 1u);
        } else {
            while (*((volatile unsigned*)&g_barGen) == gen) { }
        }
        __threadfence();
    }
    __syncthreads();
}

__global__ void __launch_bounds__(NT, 1)
fused_loss_kernel(const float* __restrict__ outputs,
                  const float* __restrict__ labels,
                  float* __restrict__ out) {
    __shared__ __align__(16) char s_raw[16384];  // union: phase2/4 scratch | phase5 B tile

    const int tidg  = blockIdx.x * NT + threadIdx.x;
    const int lane  = threadIdx.x & 31;

    // ================= Phase 1: per-row argmax + sum-of-squares =============
    {
        const int warp   = tidg >> 5;
        const int nwarps = (NB * NT) >> 5;           // 2368
        for (int r = warp; r < N_ROWS; r += nwarps) {
            // argmax over 64 labels, first-max wins on ties (jnp.argmax)
            const float* lr = labels + (size_t)r * NCLS;
            float v0 = lr[lane];
            float v1 = lr[lane + 32];
            float bv; int bi;
            if (v0 >= v1) { bv = v0; bi = lane; } else { bv = v1; bi = lane + 32; }
            #pragma unroll
            for (int s = 16; s > 0; s >>= 1) {
                float ov = __shfl_down_sync(0xffffffffu, bv, s);
                int   oi = __shfl_down_sync(0xffffffffu, bi, s);
                if (ov > bv || (ov == bv && oi < bi)) { bv = ov; bi = oi; }
            }
            bi = __shfl_sync(0xffffffffu, bi, 0);

            // sum of squares over 512 dims
            const float4* xr = (const float4*)(outputs + (size_t)r * DIM);
            float s = 0.f;
            #pragma unroll
            for (int k = lane; k < DIM / 4; k += 32) {
                float4 v = xr[k];
                s += v.x * v.x + v.y * v.y + v.z * v.z + v.w * v.w;
            }
            #pragma unroll
            for (int sh = 16; sh > 0; sh >>= 1)
                s += __shfl_down_sync(0xffffffffu, s, sh);

            if (lane == 0) {
                g_lbl[r] = bi;
                g_sq[r]  = s;
                atomicAdd(&g_hist[bi], 1);
            }
        }
    }
    grid_sync();  // #1

    // ================= Phase 2: scan histogram (block 0) =====================
    if (blockIdx.x == 0) {
        int* s_h = (int*)s_raw;
        if (threadIdx.x < NCLS) s_h[threadIdx.x] = g_hist[threadIdx.x];
        __syncthreads();
        if (threadIdx.x == 0) {
            int acc = 0, m1 = -1, m2 = -1;
            double scnt = 0.0;
            for (int c = 0; c < NCLS; c++) {
                g_off[c]    = acc;
                g_cursor[c] = acc;
                int n = s_h[c];
                acc += n;
                if (n > 0) { m2 = m1; m1 = c; }
                scnt += (double)n * (double)(n - 1) * 0.5;
            }
            g_off[NCLS] = acc;
            g_m1 = m1;
            g_m2 = m2;
            g_sameCnt = scnt;
        }
        __syncthreads();
    }
    grid_sync();  // #2

    // ================= Phase 3: scatter row indices by class =================
    if (tidg < N_ROWS) {
        int c   = g_lbl[tidg];
        int pos = atomicAdd(&g_cursor[c], 1);
        g_members[pos] = tidg;
    }
    grid_sync();  // #3

    // ====== Phase 4 (blocks 0..63)  : per-class sums -> same-class term ======
    // Sum_{i<j in c} d2 = n_c * S_c - ||M_c||^2   (max(.,0) never binds:
    // min same-pair d2 for this data is ~7e2). Data is L2-resident now.
    if (blockIdx.x < NCLS) {
        double* s_red = (double*)s_raw;            // 4KB
        int*    s_idx = (int*)(s_raw + 4096);      // 2KB
        int c   = blockIdx.x;
        int beg = g_off[c];
        int end = g_off[c + 1];
        int n   = end - beg;
        int d   = threadIdx.x;

        float m = 0.f, ssq = 0.f;
        for (int base = beg; base < end; base += NT) {
            int chunk = min(NT, end - base);
            __syncthreads();
            if (d < chunk) s_idx[d] = g_members[base + d];
            __syncthreads();
            for (int k = 0; k < chunk; k++) {
                float x = outputs[(size_t)s_idx[k] * DIM + d];
                m   += x;
                ssq += x * x;
            }
        }
        __syncthreads();

        s_red[d] = (double)m * (double)m;          // ||M||^2
        __syncthreads();
        #pragma unroll
        for (int s = 256; s > 0; s >>= 1) {
            if (d < s) s_red[d] += s_red[d + s];
            __syncthreads();
        }
        double Msq = s_red[0];
        __syncthreads();

        s_red[d] = (double)ssq;                    // S_c
        __syncthreads();
        #pragma unroll
        for (int s = 256; s > 0; s >>= 1) {
            if (d < s) s_red[d] += s_red[d + s];
            __syncthreads();
        }
        if (d == 0 && n > 1)
            atomicAdd(&g_sameSum, (double)n * s_red[0] - Msq);
    }
    // ====== Phase 5 (blocks 64..147): cross-class hinge, smem-tiled ==========
    // Tiles of 16 A-rows (class m2, one per warp, register-resident) x
    // 8 B-rows (class m1, in smem). Lane-interleaved dims -> conflict-free LDS.
    else {
        int m1 = g_m1, m2 = g_m2;
        if (m1 >= 0 && m2 >= 0) {
            int off1 = g_off[m1], n1 = g_off[m1 + 1] - off1;
            int off2 = g_off[m2], n2 = g_off[m2 + 1] - off2;
            int tI = (n2 + 15) >> 4;
            int tJ = (n1 + 7)  >> 3;
            int ntiles = tI * tJ;
            float* Bs = (float*)s_raw;             // 8 x 512 floats = 16KB
            double hsum = 0.0;

            for (int tile = (int)blockIdx.x - NCLS; tile < ntiles; tile += NB - NCLS) {
                int ti = tile / tJ, tj = tile - ti * tJ;
                int i0 = ti << 4, j0 = tj << 3;

                __syncthreads();                   // prior tile's reads done
                // cooperative B-tile load: thread t -> row t/64, 2 float4s
                {
                    int jr = threadIdx.x >> 6, q = threadIdx.x & 63;
                    int jg = j0 + jr;
                    if (jg < n1) {
                        const float4* src =
                            (const float4*)(outputs + (size_t)g_members[off1 + jg] * DIM);
                        float4* dst = (float4*)(Bs + jr * DIM);
                        dst[q * 2]     = src[q * 2];
                        dst[q * 2 + 1] = src[q * 2 + 1];
                    }
                }
                __syncthreads();

                int wid = threadIdx.x >> 5;
                int ig  = i0 + wid;
                if (ig < n2) {
                    int irow = g_members[off2 + ig];
                    const float* ar = outputs + (size_t)irow * DIM;
                    float a[16];
                    #pragma unroll
                    for (int q = 0; q < 16; q++) a[q] = ar[lane + 32 * q];
                    float sqi = g_sq[irow];

                    int jmax = min(8, n1 - j0);
                    for (int j = 0; j < jmax; j++) {
                        const float* br = Bs + j * DIM;
                        float dot = 0.f;
                        #pragma unroll
                        for (int q = 0; q < 16; q++)
                            dot += a[q] * br[lane + 32 * q];
                        #pragma unroll
                        for (int sh = 16; sh > 0; sh >>= 1)
                            dot += __shfl_down_sync(0xffffffffu, dot, sh);
                        if (lane == 0) {
                            int jrow = g_members[off1 + j0 + j];
                            float d2 = fmaxf(sqi + g_sq[jrow] - 2.f * dot, 0.f);
                            float h  = fmaxf(1.0f - sqrtf(d2), 0.f);
                            hsum += (double)h * (double)h;
                        }
                    }
                }
            }
            if (lane == 0 && hsum != 0.0) atomicAdd(&g_hingeSum, hsum);
        }
    }
    grid_sync();  // #4

    // ================= Finalize + reset state for next graph replay ==========
    if (blockIdx.x == 0) {
        if (threadIdx.x == 0) {
            double same = (g_sameCnt > 0.0) ? (g_sameSum / g_sameCnt) : 0.0;
            double total_pairs = (double)N_ROWS * (double)(N_ROWS - 1) * 0.5;
            out[0] = (float)(same + g_hingeSum / total_pairs);
            g_sameSum  = 0.0;
            g_hingeSum = 0.0;
        }
        if (threadIdx.x < NCLS) g_hist[threadIdx.x] = 0;
    }
}

extern "C" void kernel_launch(void* const* d_in, const int* in_sizes, int n_in,
                              void* d_out, int out_size) {
    const float* outputs = (const float*)d_in[0];   // [8192, 512] f32
    const float* labels  = (const float*)d_in[1];   // [8192, 64]  f32
    float* out = (float*)d_out;
    (void)in_sizes; (void)n_in; (void)out_size;

    fused_loss_kernel<<<NB, NT>>>(outputs, labels, out);
}

// round 15
// speedup vs baseline: 1.1685x; 1.0056x over previous
#include <cuda_runtime.h>
#include <cuda_bf16.h>
#include <math.h>

// Problem constants (fixed by setup_inputs: N=8192, D=512, C=64)
#define N_ROWS 8192
#define DIM    512
#define NCLS   64
#define NB     148        // persistent blocks, one per SM (GB300 has 152)
#define NT     512

// ---------------- device scratch (no allocations allowed) ----------------
__device__ int    g_lbl[N_ROWS];
__device__ float  g_sq[N_ROWS];
__device__ int    g_hist[NCLS];       // must be zero at phase-1 entry (reset at end of run)
__device__ int    g_off[NCLS + 1];
__device__ int    g_cursor[NCLS];
__device__ int    g_members[N_ROWS];
__device__ int    g_m1, g_m2;
__device__ double g_sameSum;          // reset at end of run
__device__ double g_sameCnt;
__device__ double g_hingeSum;         // reset at end of run
__device__ unsigned g_barCount = 0;   // returns to 0 after every barrier
__device__ unsigned g_barGen   = 0;   // monotonically increasing generation

// Grid-wide barrier: 1 arrival per block (single-lane REDG ~1cyc at LTS),
// spin on generation word with volatile loads (L2 reads, not atomics).
__device__ __forceinline__ void grid_sync() {
    __syncthreads();
    if (threadIdx.x == 0) {
        __threadfence();                                   // publish my writes
        unsigned gen = *((volatile unsigned*)&g_barGen);   // read BEFORE arriving
        unsigned t = atomicAdd(&g_barCount, 1u);
        if (t == NB - 1) {
            atomicExch(&g_barCount, 0u);
            __threadfence();
            atomicAdd(&g_barGen, 1u);
        } else {
            while (*((volatile unsigned*)&g_barGen) == gen) { }
        }
        __threadfence();
    }
    __syncthreads();
}

__global__ void __launch_bounds__(NT, 1)
fused_loss_kernel(const float* __restrict__ outputs,
                  const float* __restrict__ labels,
                  float* __restrict__ out) {
    __shared__ __align__(16) char s_raw[16384];  // union: phase2/4 scratch | phase5 B tile

    const int tidg  = blockIdx.x * NT + threadIdx.x;
    const int lane  = threadIdx.x & 31;

    // ================= Phase 1: per-row argmax + sum-of-squares =============
    {
        const int warp   = tidg >> 5;
        const int nwarps = (NB * NT) >> 5;           // 2368
        for (int r = warp; r < N_ROWS; r += nwarps) {
            // argmax over 64 labels, first-max wins on ties (jnp.argmax)
            const float* lr = labels + (size_t)r * NCLS;
            float v0 = lr[lane];
            float v1 = lr[lane + 32];
            float bv; int bi;
            if (v0 >= v1) { bv = v0; bi = lane; } else { bv = v1; bi = lane + 32; }
            #pragma unroll
            for (int s = 16; s > 0; s >>= 1) {
                float ov = __shfl_down_sync(0xffffffffu, bv, s);
                int   oi = __shfl_down_sync(0xffffffffu, bi, s);
                if (ov > bv || (ov == bv && oi < bi)) { bv = ov; bi = oi; }
            }
            bi = __shfl_sync(0xffffffffu, bi, 0);

            // sum of squares over 512 dims
            const float4* xr = (const float4*)(outputs + (size_t)r * DIM);
            float s = 0.f;
            #pragma unroll
            for (int k = lane; k < DIM / 4; k += 32) {
                float4 v = xr[k];
                s += v.x * v.x + v.y * v.y + v.z * v.z + v.w * v.w;
            }
            #pragma unroll
            for (int sh = 16; sh > 0; sh >>= 1)
                s += __shfl_down_sync(0xffffffffu, s, sh);

            if (lane == 0) {
                g_lbl[r] = bi;
                g_sq[r]  = s;
                atomicAdd(&g_hist[bi], 1);
            }
        }
    }
    grid_sync();  // #1

    // ================= Phase 2: scan histogram (block 0) =====================
    if (blockIdx.x == 0) {
        int* s_h = (int*)s_raw;
        if (threadIdx.x < NCLS) s_h[threadIdx.x] = g_hist[threadIdx.x];
        __syncthreads();
        if (threadIdx.x == 0) {
            int acc = 0, m1 = -1, m2 = -1;
            double scnt = 0.0;
            for (int c = 0; c < NCLS; c++) {
                g_off[c]    = acc;
                g_cursor[c] = acc;
                int n = s_h[c];
                acc += n;
                if (n > 0) { m2 = m1; m1 = c; }
                scnt += (double)n * (double)(n - 1) * 0.5;
            }
            g_off[NCLS] = acc;
            g_m1 = m1;
            g_m2 = m2;
            g_sameCnt = scnt;
        }
        __syncthreads();
    }
    grid_sync();  // #2

    // ================= Phase 3: scatter row indices by class =================
    if (tidg < N_ROWS) {
        int c   = g_lbl[tidg];
        int pos = atomicAdd(&g_cursor[c], 1);
        g_members[pos] = tidg;
    }
    grid_sync();  // #3

    // ====== Phase 4 (blocks 0..63)  : per-class sums -> same-class term ======
    // Sum_{i<j in c} d2 = n_c * S_c - ||M_c||^2   (max(.,0) never binds:
    // min same-pair d2 for this data is ~7e2). Data is L2-resident now.
    if (blockIdx.x < NCLS) {
        double* s_red = (double*)s_raw;            // 4KB
        int*    s_idx = (int*)(s_raw + 4096);      // 2KB
        int c   = blockIdx.x;
        int beg = g_off[c];
        int end = g_off[c + 1];
        int n   = end - beg;
        int d   = threadIdx.x;

        float m = 0.f, ssq = 0.f;
        for (int base = beg; base < end; base += NT) {
            int chunk = min(NT, end - base);
            __syncthreads();
            if (d < chunk) s_idx[d] = g_members[base + d];
            __syncthreads();
            for (int k = 0; k < chunk; k++) {
                float x = outputs[(size_t)s_idx[k] * DIM + d];
                m   += x;
                ssq += x * x;
            }
        }
        __syncthreads();

        s_red[d] = (double)m * (double)m;          // ||M||^2
        __syncthreads();
        #pragma unroll
        for (int s = 256; s > 0; s >>= 1) {
            if (d < s) s_red[d] += s_red[d + s];
            __syncthreads();
        }
        double Msq = s_red[0];
        __syncthreads();

        s_red[d] = (double)ssq;                    // S_c
        __syncthreads();
        #pragma unroll
        for (int s = 256; s > 0; s >>= 1) {
            if (d < s) s_red[d] += s_red[d + s];
            __syncthreads();
        }
        if (d == 0 && n > 1)
            atomicAdd(&g_sameSum, (double)n * s_red[0] - Msq);
    }
    // ====== Phase 5 (blocks 64..147): cross-class hinge, smem-tiled ==========
    // Tiles of 16 A-rows (class m2, one per warp, register-resident) x
    // 8 B-rows (class m1, in smem). Lane-interleaved dims -> conflict-free LDS.
    else {
        int m1 = g_m1, m2 = g_m2;
        if (m1 >= 0 && m2 >= 0) {
            int off1 = g_off[m1], n1 = g_off[m1 + 1] - off1;
            int off2 = g_off[m2], n2 = g_off[m2 + 1] - off2;
            int tI = (n2 + 15) >> 4;
            int tJ = (n1 + 7)  >> 3;
            int ntiles = tI * tJ;
            float* Bs = (float*)s_raw;             // 8 x 512 floats = 16KB
            double hsum = 0.0;

            for (int tile = (int)blockIdx.x - NCLS; tile < ntiles; tile += NB - NCLS) {
                int ti = tile / tJ, tj = tile - ti * tJ;
                int i0 = ti << 4, j0 = tj << 3;

                __syncthreads();                   // prior tile's reads done
                // cooperative B-tile load: thread t -> row t/64, 2 float4s
                {
                    int jr = threadIdx.x >> 6, q = threadIdx.x & 63;
                    int jg = j0 + jr;
                    if (jg < n1) {
                        const float4* src =
                            (const float4*)(outputs + (size_t)g_members[off1 + jg] * DIM);
                        float4* dst = (float4*)(Bs + jr * DIM);
                        dst[q * 2]     = src[q * 2];
                        dst[q * 2 + 1] = src[q * 2 + 1];
                    }
                }
                __syncthreads();

                int wid = threadIdx.x >> 5;
                int ig  = i0 + wid;
                if (ig < n2) {
                    int irow = g_members[off2 + ig];
                    const float* ar = outputs + (size_t)irow * DIM;
                    float a[16];
                    #pragma unroll
                    for (int q = 0; q < 16; q++) a[q] = ar[lane + 32 * q];
                    float sqi = g_sq[irow];

                    int jmax = min(8, n1 - j0);
                    for (int j = 0; j < jmax; j++) {
                        const float* br = Bs + j * DIM;
                        float dot = 0.f;
                        #pragma unroll
                        for (int q = 0; q < 16; q++)
                            dot += a[q] * br[lane + 32 * q];
                        #pragma unroll
                        for (int sh = 16; sh > 0; sh >>= 1)
                            dot += __shfl_down_sync(0xffffffffu, dot, sh);
                        if (lane == 0) {
                            int jrow = g_members[off1 + j0 + j];
                            float d2 = fmaxf(sqi + g_sq[jrow] - 2.f * dot, 0.f);
                            float h  = fmaxf(1.0f - sqrtf(d2), 0.f);
                            hsum += (double)h * (double)h;
                        }
                    }
                }
            }
            if (lane == 0 && hsum != 0.0) atomicAdd(&g_hingeSum, hsum);
        }
    }
    grid_sync();  // #4

    // ================= Finalize + reset state for next graph replay ==========
    if (blockIdx.x == 0) {
        if (threadIdx.x == 0) {
            double same = (g_sameCnt > 0.0) ? (g_sameSum / g_sameCnt) : 0.0;
            double total_pairs = (double)N_ROWS * (double)(N_ROWS - 1) * 0.5;
            out[0] = (float)(same + g_hingeSum / total_pairs);
            g_sameSum  = 0.0;
            g_hingeSum = 0.0;
        }
        if (threadIdx.x < NCLS) g_hist[threadIdx.x] = 0;
    }
}

extern "C" void kernel_launch(void* const* d_in, const int* in_sizes, int n_in,
                              void* d_out, int out_size) {
    const float* outputs = (const float*)d_in[0];   // [8192, 512] f32
    const float* labels  = (const float*)d_in[1];   // [8192, 64]  f32
    float* out = (float*)d_out;
    (void)in_sizes; (void)n_in; (void)out_size;

    fused_loss_kernel<<<NB, NT>>>(outputs, labels, out);
}

// round 16
// speedup vs baseline: 1.2235x; 1.0471x over previous
#include <cuda_runtime.h>
#include <cuda_bf16.h>
#include <math.h>

// Problem constants (fixed by setup_inputs: N=8192, D=512, C=64)
#define N_ROWS 8192
#define DIM    512
#define NCLS   64
#define NB     148        // persistent blocks, one per SM (GB300 has 152)
#define NT     512

// ---------------- device scratch (no allocations allowed) ----------------
__device__ int    g_lbl[N_ROWS];
__device__ float  g_sq[N_ROWS];
__device__ int    g_hist[NCLS];       // must be zero at phase-1 entry (reset at end of run)
__device__ int    g_off[NCLS + 1];
__device__ int    g_cursor[NCLS];
__device__ int    g_members[N_ROWS];
__device__ int    g_m1, g_m2;
__device__ double g_sameSum;          // reset at end of run
__device__ double g_sameCnt;
__device__ double g_hingeSum;         // reset at end of run
__device__ unsigned g_barCount = 0;   // returns to 0 after every barrier
__device__ unsigned g_barGen   = 0;   // monotonically increasing generation

// Grid-wide barrier: 1 arrival per block (single-lane REDG ~1cyc at LTS),
// spin on generation word with volatile loads (L2 reads, not atomics).
__device__ __forceinline__ void grid_sync() {
    __syncthreads();
    if (threadIdx.x == 0) {
        __threadfence();                                   // publish my writes
        unsigned gen = *((volatile unsigned*)&g_barGen);   // read BEFORE arriving
        unsigned t = atomicAdd(&g_barCount, 1u);
        if (t == NB - 1) {
            atomicExch(&g_barCount, 0u);
            __threadfence();
            atomicAdd(&g_barGen, 1u);
        } else {
            while (*((volatile unsigned*)&g_barGen) == gen) { }
        }
        __threadfence();
    }
    __syncthreads();
}

__global__ void __launch_bounds__(NT, 1)
fused_loss_kernel(const float* __restrict__ outputs,
                  const float* __restrict__ labels,
                  float* __restrict__ out) {
    __shared__ __align__(16) char s_raw[16384];  // union: phase2/4 scratch | phase5 B tile

    const int tidg  = blockIdx.x * NT + threadIdx.x;
    const int lane  = threadIdx.x & 31;

    // ================= Phase 1: per-row argmax + sum-of-squares =============
    {
        const int warp   = tidg >> 5;
        const int nwarps = (NB * NT) >> 5;           // 2368
        for (int r = warp; r < N_ROWS; r += nwarps) {
            // argmax over 64 labels, first-max wins on ties (jnp.argmax)
            const float* lr = labels + (size_t)r * NCLS;
            float v0 = lr[lane];
            float v1 = lr[lane + 32];
            float bv; int bi;
            if (v0 >= v1) { bv = v0; bi = lane; } else { bv = v1; bi = lane + 32; }
            #pragma unroll
            for (int s = 16; s > 0; s >>= 1) {
                float ov = __shfl_down_sync(0xffffffffu, bv, s);
                int   oi = __shfl_down_sync(0xffffffffu, bi, s);
                if (ov > bv || (ov == bv && oi < bi)) { bv = ov; bi = oi; }
            }
            bi = __shfl_sync(0xffffffffu, bi, 0);

            // sum of squares over 512 dims
            const float4* xr = (const float4*)(outputs + (size_t)r * DIM);
            float s = 0.f;
            #pragma unroll
            for (int k = lane; k < DIM / 4; k += 32) {
                float4 v = xr[k];
                s += v.x * v.x + v.y * v.y + v.z * v.z + v.w * v.w;
            }
            #pragma unroll
            for (int sh = 16; sh > 0; sh >>= 1)
                s += __shfl_down_sync(0xffffffffu, s, sh);

            if (lane == 0) {
                g_lbl[r] = bi;
                g_sq[r]  = s;
                atomicAdd(&g_hist[bi], 1);
            }
        }
    }
    grid_sync();  // #1

    // ================= Phase 2: scan histogram (block 0) =====================
    if (blockIdx.x == 0) {
        int* s_h = (int*)s_raw;
        if (threadIdx.x < NCLS) s_h[threadIdx.x] = g_hist[threadIdx.x];
        __syncthreads();
        if (threadIdx.x == 0) {
            int acc = 0, m1 = -1, m2 = -1;
            double scnt = 0.0;
            for (int c = 0; c < NCLS; c++) {
                g_off[c]    = acc;
                g_cursor[c] = acc;
                int n = s_h[c];
                acc += n;
                if (n > 0) { m2 = m1; m1 = c; }
                scnt += (double)n * (double)(n - 1) * 0.5;
            }
            g_off[NCLS] = acc;
            g_m1 = m1;
            g_m2 = m2;
            g_sameCnt = scnt;
        }
        __syncthreads();
    }
    grid_sync();  // #2

    // ================= Phase 3: scatter row indices by class =================
    if (tidg < N_ROWS) {
        int c   = g_lbl[tidg];
        int pos = atomicAdd(&g_cursor[c], 1);
        g_members[pos] = tidg;
    }
    grid_sync();  // #3

    // ====== Phase 4 (blocks 0..63)  : per-class sums -> same-class term ======
    // Sum_{i<j in c} d2 = n_c * S_c - ||M_c||^2   (max(.,0) never binds:
    // min same-pair d2 for this data is ~7e2). Data is L2-resident now.
    if (blockIdx.x < NCLS) {
        double* s_red = (double*)s_raw;            // 4KB
        int*    s_idx = (int*)(s_raw + 4096);      // 2KB
        int c   = blockIdx.x;
        int beg = g_off[c];
        int end = g_off[c + 1];
        int n   = end - beg;
        int d   = threadIdx.x;

        float m = 0.f, ssq = 0.f;
        for (int base = beg; base < end; base += NT) {
            int chunk = min(NT, end - base);
            __syncthreads();
            if (d < chunk) s_idx[d] = g_members[base + d];
            __syncthreads();
            for (int k = 0; k < chunk; k++) {
                float x = outputs[(size_t)s_idx[k] * DIM + d];
                m   += x;
                ssq += x * x;
            }
        }
        __syncthreads();

        s_red[d] = (double)m * (double)m;          // ||M||^2
        __syncthreads();
        #pragma unroll
        for (int s = 256; s > 0; s >>= 1) {
            if (d < s) s_red[d] += s_red[d + s];
            __syncthreads();
        }
        double Msq = s_red[0];
        __syncthreads();

        s_red[d] = (double)ssq;                    // S_c
        __syncthreads();
        #pragma unroll
        for (int s = 256; s > 0; s >>= 1) {
            if (d < s) s_red[d] += s_red[d + s];
            __syncthreads();
        }
        if (d == 0 && n > 1)
            atomicAdd(&g_sameSum, (double)n * s_red[0] - Msq);
    }
    // ====== Phase 5 (blocks 64..147): cross-class hinge, smem-tiled ==========
    // Tiles of 16 A-rows (class m2, one per warp, register-resident) x
    // 8 B-rows (class m1, in smem). Lane-interleaved dims -> conflict-free LDS.
    else {
        int m1 = g_m1, m2 = g_m2;
        if (m1 >= 0 && m2 >= 0) {
            int off1 = g_off[m1], n1 = g_off[m1 + 1] - off1;
            int off2 = g_off[m2], n2 = g_off[m2 + 1] - off2;
            int tI = (n2 + 15) >> 4;
            int tJ = (n1 + 7)  >> 3;
            int ntiles = tI * tJ;
            float* Bs = (float*)s_raw;             // 8 x 512 floats = 16KB
            double hsum = 0.0;

            for (int tile = (int)blockIdx.x - NCLS; tile < ntiles; tile += NB - NCLS) {
                int ti = tile / tJ, tj = tile - ti * tJ;
                int i0 = ti << 4, j0 = tj << 3;

                __syncthreads();                   // prior tile's reads done
                // cooperative B-tile load: thread t -> row t/64, 2 float4s
                {
                    int jr = threadIdx.x >> 6, q = threadIdx.x & 63;
                    int jg = j0 + jr;
                    if (jg < n1) {
                        const float4* src =
                            (const float4*)(outputs + (size_t)g_members[off1 + jg] * DIM);
                        float4* dst = (float4*)(Bs + jr * DIM);
                        dst[q * 2]     = src[q * 2];
                        dst[q * 2 + 1] = src[q * 2 + 1];
                    }
                }
                __syncthreads();

                int wid = threadIdx.x >> 5;
                int ig  = i0 + wid;
                if (ig < n2) {
                    int irow = g_members[off2 + ig];
                    const float* ar = outputs + (size_t)irow * DIM;
                    float a[16];
                    #pragma unroll
                    for (int q = 0; q < 16; q++) a[q] = ar[lane + 32 * q];
                    float sqi = g_sq[irow];

                    int jmax = min(8, n1 - j0);
                    for (int j = 0; j < jmax; j++) {
                        const float* br = Bs + j * DIM;
                        float dot = 0.f;
                        #pragma unroll
                        for (int q = 0; q < 16; q++)
                            dot += a[q] * br[lane + 32 * q];
                        #pragma unroll
                        for (int sh = 16; sh > 0; sh >>= 1)
                            dot += __shfl_down_sync(0xffffffffu, dot, sh);
                        if (lane == 0) {
                            int jrow = g_members[off1 + j0 + j];
                            float d2 = fmaxf(sqi + g_sq[jrow] - 2.f * dot, 0.f);
                            float h  = fmaxf(1.0f - sqrtf(d2), 0.f);
                            hsum += (double)h * (double)h;
                        }
                    }
                }
            }
            if (lane == 0 && hsum != 0.0) atomicAdd(&g_hingeSum, hsum);
        }
    }
    grid_sync();  // #4

    // ================= Finalize + reset state for next graph replay ==========
    if (blockIdx.x == 0) {
        if (threadIdx.x == 0) {
            double same = (g_sameCnt > 0.0) ? (g_sameSum / g_sameCnt) : 0.0;
            double total_pairs = (double)N_ROWS * (double)(N_ROWS - 1) * 0.5;
            out[0] = (float)(same + g_hingeSum / total_pairs);
            g_sameSum  = 0.0;
            g_hingeSum = 0.0;
        }
        if (threadIdx.x < NCLS) g_hist[threadIdx.x] = 0;
    }
}

extern "C" void kernel_launch(void* const* d_in, const int* in_sizes, int n_in,
                              void* d_out, int out_size) {
    const float* outputs = (const float*)d_in[0];   // [8192, 512] f32
    const float* labels  = (const float*)d_in[1];   // [8192, 64]  f32
    float* out = (float*)d_out;
    (void)in_sizes; (void)n_in; (void)out_size;

    fused_loss_kernel<<<NB, NT>>>(outputs, labels, out);
}

// round 17
// speedup vs baseline: 1.2244x; 1.0007x over previous
#include <cuda_runtime.h>
#include <cuda_bf16.h>
#include <math.h>

// Problem constants (fixed by setup_inputs: N=8192, D=512, C=64)
#define N_ROWS 8192
#define DIM    512
#define NCLS   64
#define NB     148        // persistent blocks, one per SM (GB300 has 152)
#define NT     512

// ---------------- device scratch (no allocations allowed) ----------------
__device__ int    g_lbl[N_ROWS];
__device__ float  g_sq[N_ROWS];
__device__ int    g_hist[NCLS];       // must be zero at phase-1 entry (reset at end of run)
__device__ int    g_off[NCLS + 1];
__device__ int    g_cursor[NCLS];
__device__ int    g_members[N_ROWS];
__device__ int    g_m1, g_m2;
__device__ double g_sameSum;          // reset at end of run
__device__ double g_sameCnt;
__device__ double g_hingeSum;         // reset at end of run
__device__ unsigned g_barCount = 0;   // returns to 0 after every barrier
__device__ unsigned g_barGen   = 0;   // monotonically increasing generation

// Grid-wide barrier: 1 arrival per block (single-lane REDG ~1cyc at LTS),
// spin on generation word with volatile loads (L2 reads, not atomics).
__device__ __forceinline__ void grid_sync() {
    __syncthreads();
    if (threadIdx.x == 0) {
        __threadfence();                                   // publish my writes
        unsigned gen = *((volatile unsigned*)&g_barGen);   // read BEFORE arriving
        unsigned t = atomicAdd(&g_barCount, 1u);
        if (t == NB - 1) {
            atomicExch(&g_barCount, 0u);
            __threadfence();
            atomicAdd(&g_barGen, 1u);
        } else {
            while (*((volatile unsigned*)&g_barGen) == gen) { }
        }
        __threadfence();
    }
    __syncthreads();
}

__global__ void __launch_bounds__(NT, 1)
fused_loss_kernel(const float* __restrict__ outputs,
                  const float* __restrict__ labels,
                  float* __restrict__ out) {
    __shared__ __align__(16) char s_raw[16384];  // union: phase2/4 scratch | phase5 B tile

    const int tidg  = blockIdx.x * NT + threadIdx.x;
    const int lane  = threadIdx.x & 31;

    // ================= Phase 1: per-row argmax + sum-of-squares =============
    {
        const int warp   = tidg >> 5;
        const int nwarps = (NB * NT) >> 5;           // 2368
        for (int r = warp; r < N_ROWS; r += nwarps) {
            // argmax over 64 labels, first-max wins on ties (jnp.argmax)
            const float* lr = labels + (size_t)r * NCLS;
            float v0 = lr[lane];
            float v1 = lr[lane + 32];
            float bv; int bi;
            if (v0 >= v1) { bv = v0; bi = lane; } else { bv = v1; bi = lane + 32; }
            #pragma unroll
            for (int s = 16; s > 0; s >>= 1) {
                float ov = __shfl_down_sync(0xffffffffu, bv, s);
                int   oi = __shfl_down_sync(0xffffffffu, bi, s);
                if (ov > bv || (ov == bv && oi < bi)) { bv = ov; bi = oi; }
            }
            bi = __shfl_sync(0xffffffffu, bi, 0);

            // sum of squares over 512 dims
            const float4* xr = (const float4*)(outputs + (size_t)r * DIM);
            float s = 0.f;
            #pragma unroll
            for (int k = lane; k < DIM / 4; k += 32) {
                float4 v = xr[k];
                s += v.x * v.x + v.y * v.y + v.z * v.z + v.w * v.w;
            }
            #pragma unroll
            for (int sh = 16; sh > 0; sh >>= 1)
                s += __shfl_down_sync(0xffffffffu, s, sh);

            if (lane == 0) {
                g_lbl[r] = bi;
                g_sq[r]  = s;
                atomicAdd(&g_hist[bi], 1);
            }
        }
    }
    grid_sync();  // #1

    // ================= Phase 2: scan histogram (block 0) =====================
    if (blockIdx.x == 0) {
        int* s_h = (int*)s_raw;
        if (threadIdx.x < NCLS) s_h[threadIdx.x] = g_hist[threadIdx.x];
        __syncthreads();
        if (threadIdx.x == 0) {
            int acc = 0, m1 = -1, m2 = -1;
            double scnt = 0.0;
            for (int c = 0; c < NCLS; c++) {
                g_off[c]    = acc;
                g_cursor[c] = acc;
                int n = s_h[c];
                acc += n;
                if (n > 0) { m2 = m1; m1 = c; }
                scnt += (double)n * (double)(n - 1) * 0.5;
            }
            g_off[NCLS] = acc;
            g_m1 = m1;
            g_m2 = m2;
            g_sameCnt = scnt;
        }
        __syncthreads();
    }
    grid_sync();  // #2

    // ================= Phase 3: scatter row indices by class =================
    if (tidg < N_ROWS) {
        int c   = g_lbl[tidg];
        int pos = atomicAdd(&g_cursor[c], 1);
        g_members[pos] = tidg;
    }
    grid_sync();  // #3

    // ====== Phase 4 (blocks 0..63)  : per-class sums -> same-class term ======
    // Sum_{i<j in c} d2 = n_c * S_c - ||M_c||^2   (max(.,0) never binds:
    // min same-pair d2 for this data is ~7e2). Data is L2-resident now.
    if (blockIdx.x < NCLS) {
        double* s_red = (double*)s_raw;            // 4KB
        int*    s_idx = (int*)(s_raw + 4096);      // 2KB
        int c   = blockIdx.x;
        int beg = g_off[c];
        int end = g_off[c + 1];
        int n   = end - beg;
        int d   = threadIdx.x;

        float m = 0.f, ssq = 0.f;
        for (int base = beg; base < end; base += NT) {
            int chunk = min(NT, end - base);
            __syncthreads();
            if (d < chunk) s_idx[d] = g_members[base + d];
            __syncthreads();
            for (int k = 0; k < chunk; k++) {
                float x = outputs[(size_t)s_idx[k] * DIM + d];
                m   += x;
                ssq += x * x;
            }
        }
        __syncthreads();

        s_red[d] = (double)m * (double)m;          // ||M||^2
        __syncthreads();
        #pragma unroll
        for (int s = 256; s > 0; s >>= 1) {
            if (d < s) s_red[d] += s_red[d + s];
            __syncthreads();
        }
        double Msq = s_red[0];
        __syncthreads();

        s_red[d] = (double)ssq;                    // S_c
        __syncthreads();
        #pragma unroll
        for (int s = 256; s > 0; s >>= 1) {
            if (d < s) s_red[d] += s_red[d + s];
            __syncthreads();
        }
        if (d == 0 && n > 1)
            atomicAdd(&g_sameSum, (double)n * s_red[0] - Msq);
    }
    // ====== Phase 5 (blocks 64..147): cross-class hinge, smem-tiled ==========
    // Tiles of 16 A-rows (class m2, one per warp, register-resident) x
    // 8 B-rows (class m1, in smem). Lane-interleaved dims -> conflict-free LDS.
    else {
        int m1 = g_m1, m2 = g_m2;
        if (m1 >= 0 && m2 >= 0) {
            int off1 = g_off[m1], n1 = g_off[m1 + 1] - off1;
            int off2 = g_off[m2], n2 = g_off[m2 + 1] - off2;
            int tI = (n2 + 15) >> 4;
            int tJ = (n1 + 7)  >> 3;
            int ntiles = tI * tJ;
            float* Bs = (float*)s_raw;             // 8 x 512 floats = 16KB
            double hsum = 0.0;

            for (int tile = (int)blockIdx.x - NCLS; tile < ntiles; tile += NB - NCLS) {
                int ti = tile / tJ, tj = tile - ti * tJ;
                int i0 = ti << 4, j0 = tj << 3;

                __syncthreads();                   // prior tile's reads done
                // cooperative B-tile load: thread t -> row t/64, 2 float4s
                {
                    int jr = threadIdx.x >> 6, q = threadIdx.x & 63;
                    int jg = j0 + jr;
                    if (jg < n1) {
                        const float4* src =
                            (const float4*)(outputs + (size_t)g_members[off1 + jg] * DIM);
                        float4* dst = (float4*)(Bs + jr * DIM);
                        dst[q * 2]     = src[q * 2];
                        dst[q * 2 + 1] = src[q * 2 + 1];
                    }
                }
                __syncthreads();

                int wid = threadIdx.x >> 5;
                int ig  = i0 + wid;
                if (ig < n2) {
                    int irow = g_members[off2 + ig];
                    const float* ar = outputs + (size_t)irow * DIM;
                    float a[16];
                    #pragma unroll
                    for (int q = 0; q < 16; q++) a[q] = ar[lane + 32 * q];
                    float sqi = g_sq[irow];

                    int jmax = min(8, n1 - j0);
                    for (int j = 0; j < jmax; j++) {
                        const float* br = Bs + j * DIM;
                        float dot = 0.f;
                        #pragma unroll
                        for (int q = 0; q < 16; q++)
                            dot += a[q] * br[lane + 32 * q];
                        #pragma unroll
                        for (int sh = 16; sh > 0; sh >>= 1)
                            dot += __shfl_down_sync(0xffffffffu, dot, sh);
                        if (lane == 0) {
                            int jrow = g_members[off1 + j0 + j];
                            float d2 = fmaxf(sqi + g_sq[jrow] - 2.f * dot, 0.f);
                            float h  = fmaxf(1.0f - sqrtf(d2), 0.f);
                            hsum += (double)h * (double)h;
                        }
                    }
                }
            }
            if (lane == 0 && hsum != 0.0) atomicAdd(&g_hingeSum, hsum);
        }
    }
    grid_sync();  // #4

    // ================= Finalize + reset state for next graph replay ==========
    if (blockIdx.x == 0) {
        if (threadIdx.x == 0) {
            double same = (g_sameCnt > 0.0) ? (g_sameSum / g_sameCnt) : 0.0;
            double total_pairs = (double)N_ROWS * (double)(N_ROWS - 1) * 0.5;
            out[0] = (float)(same + g_hingeSum / total_pairs);
            g_sameSum  = 0.0;
            g_hingeSum = 0.0;
        }
        if (threadIdx.x < NCLS) g_hist[threadIdx.x] = 0;
    }
}

extern "C" void kernel_launch(void* const* d_in, const int* in_sizes, int n_in,
                              void* d_out, int out_size) {
    const float* outputs = (const float*)d_in[0];   // [8192, 512] f32
    const float* labels  = (const float*)d_in[1];   // [8192, 64]  f32
    float* out = (float*)d_out;
    (void)in_sizes; (void)n_in; (void)out_size;

    fused_loss_kernel<<<NB, NT>>>(outputs, labels, out);
}